// round 7
// baseline (speedup 1.0000x reference)
#include <cuda_runtime.h>
#include <cuda_fp16.h>
#include <cstdint>

#define REL_CONTEXT 0.2f

// ---------------- problem dims (fixed) ----------------
#define NROWS 8192
#define DIM   2048
#define BM    128
#define BN    256
#define BK    64
#define NCH   (DIM / BK)       // 32
#define NSTAGE 4

// ---------------- scratch (chunk-major, pre-swizzled fp16) ----------------
__device__ __align__(128) __half g_Ah[(size_t)NROWS * DIM];
__device__ __align__(128) __half g_Wh[(size_t)DIM * DIM];
__device__ float g_zeta;

// ---------------- PTX helpers (base-target only) ----------------
__device__ __forceinline__ uint32_t smem_to_u32(const void* p) {
    uint32_t a;
    asm("{ .reg .u64 t; cvta.to.shared.u64 t, %1; cvt.u32.u64 %0, t; }"
        : "=r"(a) : "l"(p));
    return a;
}
#define MBARRIER_INIT(addr, cnt) \
    asm volatile("mbarrier.init.shared.b64 [%0], %1;" :: "r"((uint32_t)(addr)), "r"((uint32_t)(cnt)) : "memory")
#define MBARRIER_ARRIVE(addr) \
    asm volatile("mbarrier.arrive.shared.b64 _, [%0];" :: "r"((uint32_t)(addr)) : "memory")
#define MBARRIER_EXPECT_TX(addr, bytes) \
    asm volatile("mbarrier.arrive.expect_tx.shared.b64 _, [%0], %1;" \
                 :: "r"((uint32_t)(addr)), "r"((uint32_t)(bytes)) : "memory")
#define MBARRIER_WAIT_PARITY(addr, par) do { \
    uint32_t _m = (uint32_t)(addr); uint32_t _p = (uint32_t)(par); uint32_t _d; \
    asm volatile("{\n\t.reg .pred p;\n\t" \
        "mbarrier.try_wait.parity.acquire.cta.shared::cta.b64 p, [%1], %2;\n\t" \
        "selp.b32 %0, 1, 0, p;\n\t}" : "=r"(_d) : "r"(_m), "r"(_p) : "memory"); \
    if (!_d) { \
        asm volatile("{\n\t.reg .pred P1;\n\t" \
            "WL_%=:\n\t" \
            "mbarrier.try_wait.parity.acquire.cta.shared::cta.b64 P1, [%0], %1, 0x989680;\n\t" \
            "@P1 bra.uni WD_%=;\n\tbra.uni WL_%=;\n\tWD_%=:\n\t}" \
            :: "r"(_m), "r"(_p) : "memory"); \
    } } while (0)
#define BULK_G2S(dst, src, bytes, mbar) \
    asm volatile("cp.async.bulk.shared::cluster.global.mbarrier::complete_tx::bytes " \
                 "[%0], [%1], %2, [%3];" \
                 :: "r"((uint32_t)(dst)), "l"(src), "r"((uint32_t)(bytes)), \
                    "r"((uint32_t)(mbar)) : "memory")
#define LDMATRIX_X4(r0, r1, r2, r3, addr) \
    asm volatile("ldmatrix.sync.aligned.m8n8.x4.shared.b16 {%0,%1,%2,%3}, [%4];" \
                 : "=r"(r0), "=r"(r1), "=r"(r2), "=r"(r3) : "r"(addr))
#define MMA_F16(d, a, b) \
    asm volatile("mma.sync.aligned.m16n8k16.row.col.f32.f16.f16.f32 " \
                 "{%0,%1,%2,%3}, {%4,%5,%6,%7}, {%8,%9}, {%0,%1,%2,%3};" \
                 : "+f"((d)[0]), "+f"((d)[1]), "+f"((d)[2]), "+f"((d)[3]) \
                 : "r"((a)[0]), "r"((a)[1]), "r"((a)[2]), "r"((a)[3]), \
                   "r"((b)[0]), "r"((b)[1]))

// ---------------- smem layout ----------------
#define SM_BAR   0                    // full[s] at 16*s, empty[s] at 16*s+8
#define SM_BIAS  256                  // 256 floats (1KB)
#define SM_TILES 2048
#define T_AH     0                    // 16 KB
#define T_BH     16384                // 32 KB
#define STAGE_BYTES 49152
#define SMEM_TOTAL (SM_TILES + NSTAGE * STAGE_BYTES)   // 198656 (1 CTA/SM)

// chunk-major, swizzled byte offset for (row, k0): 4 consecutive halves (8B)
__device__ __forceinline__ size_t scratch_off(int nTotRows, int row, int k0) {
    const int chunk = k0 >> 6;
    const int kc = k0 & 63;
    const int ci = kc >> 3;
    const int h8 = (kc >> 2) & 1;
    return ((size_t)chunk * nTotRows + row) * 128 + ((ci ^ (row & 7)) << 4) + h8 * 8;
}

__device__ __forceinline__ uint2 pack_h4(const float v[4]) {
    uint16_t h[4];
    #pragma unroll
    for (int i = 0; i < 4; i++) {
        __half hv = __float2half_rn(v[i]);
        h[i] = *(uint16_t*)&hv;
    }
    return make_uint2((uint32_t)h[0] | ((uint32_t)h[1] << 16),
                      (uint32_t)h[2] | ((uint32_t)h[3] << 16));
}

// ---------------- merged prep kernel (4 rows/block, MLP>=4 per thread) ----
#define XBLK (NROWS / 4)       // 2048
#define WBLK (DIM / 4)         // 512
__global__ void prep_all(const float* __restrict__ x,
                         const int* __restrict__ ids,
                         const float* __restrict__ emb,
                         const float* __restrict__ Wt,
                         const float* __restrict__ Wrc,
                         const float* __restrict__ brc) {
    const int b = blockIdx.x;
    const int c4 = threadIdx.x;           // 512 threads = 512 float4 per row
    if (b < XBLK) {
        const int row0 = b * 4;
        float4 xv[4], ev[4];
        int id[4];
        #pragma unroll
        for (int r = 0; r < 4; r++) {
            id[r] = ids[row0 + r];
            xv[r] = ((const float4*)(x + (size_t)(row0 + r) * DIM))[c4];
        }
        #pragma unroll
        for (int r = 0; r < 4; r++)
            ev[r] = ((const float4*)(emb + (size_t)id[r] * DIM))[c4];
        #pragma unroll
        for (int r = 0; r < 4; r++) {
            float v[4] = {xv[r].x + ev[r].x, xv[r].y + ev[r].y,
                          xv[r].z + ev[r].z, xv[r].w + ev[r].w};
            *(uint2*)((char*)g_Ah + scratch_off(NROWS, row0 + r, c4 * 4)) = pack_h4(v);
        }
    } else if (b < XBLK + WBLK) {
        const int row0 = (b - XBLK) * 4;
        float4 wv[4];
        #pragma unroll
        for (int r = 0; r < 4; r++)
            wv[r] = ((const float4*)(Wt + (size_t)(row0 + r) * DIM))[c4];
        #pragma unroll
        for (int r = 0; r < 4; r++) {
            float v[4] = {wv[r].x, wv[r].y, wv[r].z, wv[r].w};
            *(uint2*)((char*)g_Wh + scratch_off(DIM, row0 + r, c4 * 4)) = pack_h4(v);
        }
    } else {
        __shared__ float red[32];
        float s = 0.f;
        for (int i = c4; i < DIM; i += 512) s += Wrc[i];
        #pragma unroll
        for (int o = 16; o > 0; o >>= 1) s += __shfl_down_sync(0xffffffffu, s, o);
        if ((c4 & 31) == 0) red[c4 >> 5] = s;
        __syncthreads();
        if (c4 < 32) {
            float v = (c4 < 16) ? red[c4] : 0.f;
            #pragma unroll
            for (int o = 8; o > 0; o >>= 1) v += __shfl_down_sync(0xffffffffu, v, o);
            if (c4 == 0)
                g_zeta = 1.f / (1.f + expf(-(REL_CONTEXT * v + brc[0])));
        }
    }
}

// ---------------- main MMA kernel: 128x256 tile, 16 warps ----------------
__global__ __launch_bounds__(512, 1)
void redaf_mma(const float* __restrict__ mw,
               const float* __restrict__ bt,
               float* __restrict__ out) {
    extern __shared__ char smem[];
    const uint32_t sb = smem_to_u32(smem);
    const int tid = threadIdx.x;
    const int wid = tid >> 5;
    const int lid = tid & 31;

    const int colBase = blockIdx.x * BN;
    const int rowBase = blockIdx.y * BM;

    if (tid == 0) {
        #pragma unroll
        for (int s = 0; s < NSTAGE; s++) {
            MBARRIER_INIT(sb + SM_BAR + 16 * s, 1);        // full: expect_tx
            MBARRIER_INIT(sb + SM_BAR + 16 * s + 8, 16);   // empty: 16 warps
        }
    }
    if (tid < BN) ((float*)(smem + SM_BIAS))[tid] = bt[colBase + tid];
    __syncthreads();

    // ---- producer: 2 bulk copies (16KB A + 32KB B) per chunk ----
    auto produce = [&](int c) {
        const int s = c & 3;
        const uint32_t stB = sb + SM_TILES + s * STAGE_BYTES;
        const uint32_t fb = sb + SM_BAR + 16 * s;
        MBARRIER_EXPECT_TX(fb, STAGE_BYTES);
        BULK_G2S(stB + T_AH,
                 (const char*)g_Ah + ((size_t)c * NROWS + rowBase) * 128, 16384, fb);
        BULK_G2S(stB + T_BH,
                 (const char*)g_Wh + ((size_t)c * DIM + colBase) * 128, 32768, fb);
    };

    // prefill chunks 0..2 into stages 0..2 (chunk 3 produced in iteration 0)
    if (lid == 0 && wid < NSTAGE - 1) produce(wid);

    // ---- warp grid: 4(M) x 4(N); warp tile 32x64 ----
    const int warpM = wid & 3;
    const int warpN = wid >> 2;
    const int aRowL = warpM * 32 + (lid & 15);
    const int aKhalf = lid >> 4;
    const int bRowL = warpN * 64 + (lid & 7) + ((lid >> 4) & 1) * 8;
    const int bKhalf = (lid >> 3) & 1;

    float acc[2][8][4];
    #pragma unroll
    for (int i = 0; i < 2; i++)
        #pragma unroll
        for (int j = 0; j < 8; j++)
            #pragma unroll
            for (int k = 0; k < 4; k++) acc[i][j][k] = 0.f;

    #pragma unroll 1
    for (int c = 0; c < NCH; c++) {
        const int s = c & 3;
        const uint32_t par = (c >> 2) & 1;
        const uint32_t fullB = sb + SM_BAR + 16 * s;
        const uint32_t emptyB = fullB + 8;
        MBARRIER_WAIT_PARITY(fullB, par);

        const uint32_t stBase = sb + SM_TILES + s * STAGE_BYTES;
        #pragma unroll
        for (int ks = 0; ks < BK / 16; ks++) {
            uint32_t ah[2][4], bh[8][2];
            #pragma unroll
            for (int mt = 0; mt < 2; mt++) {
                const int row = aRowL + mt * 16;
                const int ch = 2 * ks + aKhalf;
                const uint32_t off = row * 128 + ((ch ^ (row & 7)) << 4);
                LDMATRIX_X4(ah[mt][0], ah[mt][1], ah[mt][2], ah[mt][3],
                            stBase + T_AH + off);
            }
            #pragma unroll
            for (int p = 0; p < 4; p++) {
                const int row = bRowL + p * 16;
                const int ch = 2 * ks + bKhalf;
                const uint32_t off = row * 128 + ((ch ^ (row & 7)) << 4);
                LDMATRIX_X4(bh[2 * p][0], bh[2 * p][1], bh[2 * p + 1][0], bh[2 * p + 1][1],
                            stBase + T_BH + off);
            }
            #pragma unroll
            for (int mt = 0; mt < 2; mt++)
                #pragma unroll
                for (int nt = 0; nt < 8; nt++) MMA_F16(acc[mt][nt], ah[mt], bh[nt]);
        }

        if (lid == 0) {
            MBARRIER_ARRIVE(emptyB);                // this warp done with chunk c
            // produce chunk c+3 into stage t=(c+3)&3; its prior occupant was
            // chunk c-1, whose readers arrived at the end of iteration c-1.
            const int t = (c + 3) & 3;
            if (wid == t && c + 3 < NCH) {
                if (c + 3 >= NSTAGE) {              // stage t had prior readers
                    MBARRIER_WAIT_PARITY(sb + SM_BAR + 16 * t + 8,
                                         (uint32_t)(((c - 1) >> 2) & 1));
                }
                produce(c + 3);
            }
        }
    }

    // ---- epilogue: bias -> relu -> mw*zeta -> relu ----
    const float zeta = g_zeta;
    const float mwz0 = mw[0] * zeta;
    const float mwz1 = mw[1] * zeta;
    const float* bsm = (const float*)(smem + SM_BIAS);

    #pragma unroll
    for (int mt = 0; mt < 2; mt++) {
        #pragma unroll
        for (int nt = 0; nt < 8; nt++) {
            const int m0 = rowBase + warpM * 32 + mt * 16 + (lid >> 2);
            const int cLoc = warpN * 64 + nt * 8 + 2 * (lid & 3);
            const float b0 = bsm[cLoc], b1 = bsm[cLoc + 1];
            const float mz = (m0 & 1) ? mwz1 : mwz0;
            float2 o0, o1;
            o0.x = fmaxf(mz * fmaxf(acc[mt][nt][0] + b0, 0.f), 0.f);
            o0.y = fmaxf(mz * fmaxf(acc[mt][nt][1] + b1, 0.f), 0.f);
            o1.x = fmaxf(mz * fmaxf(acc[mt][nt][2] + b0, 0.f), 0.f);
            o1.y = fmaxf(mz * fmaxf(acc[mt][nt][3] + b1, 0.f), 0.f);
            float* p0 = out + (size_t)m0 * DIM + colBase + cLoc;
            *(float2*)p0 = o0;
            *(float2*)(p0 + (size_t)8 * DIM) = o1;
        }
    }
}

// ---------------- launch ----------------
extern "C" void kernel_launch(void* const* d_in, const int* in_sizes, int n_in,
                              void* d_out, int out_size) {
    const float* x   = (const float*)d_in[0];
    const int*   ids = (const int*)  d_in[1];
    const float* mw  = (const float*)d_in[2];
    const float* emb = (const float*)d_in[3];
    const float* Wt  = (const float*)d_in[4];
    const float* bt  = (const float*)d_in[5];
    const float* Wrc = (const float*)d_in[6];
    const float* brc = (const float*)d_in[7];

    cudaFuncSetAttribute(redaf_mma, cudaFuncAttributeMaxDynamicSharedMemorySize,
                         SMEM_TOTAL);

    prep_all<<<XBLK + WBLK + 1, 512>>>(x, ids, emb, Wt, Wrc, brc);

    dim3 grid(DIM / BN, NROWS / BM);   // (8, 64) = 512 CTAs
    redaf_mma<<<grid, 512, SMEM_TOTAL>>>(mw, bt, (float*)d_out);
}

// round 8
// speedup vs baseline: 1.1211x; 1.1211x over previous
#include <cuda_runtime.h>
#include <cuda_fp16.h>
#include <cstdint>

#define REL_CONTEXT 0.2f

// ---------------- problem dims (fixed) ----------------
#define NROWS 8192
#define DIM   2048
#define BM    128
#define BN    128
#define BK    64
#define NCH   (DIM / BK)       // 32
#define NSTAGE 3

// ---------------- scratch (chunk-major, pre-swizzled fp16) ----------------
__device__ __align__(128) __half g_Ah[(size_t)NROWS * DIM];
__device__ __align__(128) __half g_Wh[(size_t)DIM * DIM];
__device__ float g_zeta;

// ---------------- PTX helpers (base-target only) ----------------
__device__ __forceinline__ uint32_t smem_to_u32(const void* p) {
    uint32_t a;
    asm("{ .reg .u64 t; cvta.to.shared.u64 t, %1; cvt.u32.u64 %0, t; }"
        : "=r"(a) : "l"(p));
    return a;
}
#define MBARRIER_INIT(addr, cnt) \
    asm volatile("mbarrier.init.shared.b64 [%0], %1;" :: "r"((uint32_t)(addr)), "r"((uint32_t)(cnt)) : "memory")
#define MBARRIER_ARRIVE(addr) \
    asm volatile("mbarrier.arrive.shared.b64 _, [%0];" :: "r"((uint32_t)(addr)) : "memory")
#define MBARRIER_EXPECT_TX(addr, bytes) \
    asm volatile("mbarrier.arrive.expect_tx.shared.b64 _, [%0], %1;" \
                 :: "r"((uint32_t)(addr)), "r"((uint32_t)(bytes)) : "memory")
#define MBARRIER_WAIT_PARITY(addr, par) do { \
    uint32_t _m = (uint32_t)(addr); uint32_t _p = (uint32_t)(par); uint32_t _d; \
    asm volatile("{\n\t.reg .pred p;\n\t" \
        "mbarrier.try_wait.parity.acquire.cta.shared::cta.b64 p, [%1], %2;\n\t" \
        "selp.b32 %0, 1, 0, p;\n\t}" : "=r"(_d) : "r"(_m), "r"(_p) : "memory"); \
    if (!_d) { \
        asm volatile("{\n\t.reg .pred P1;\n\t" \
            "WL_%=:\n\t" \
            "mbarrier.try_wait.parity.acquire.cta.shared::cta.b64 P1, [%0], %1, 0x989680;\n\t" \
            "@P1 bra.uni WD_%=;\n\tbra.uni WL_%=;\n\tWD_%=:\n\t}" \
            :: "r"(_m), "r"(_p) : "memory"); \
    } } while (0)
#define BULK_G2S(dst, src, bytes, mbar) \
    asm volatile("cp.async.bulk.shared::cluster.global.mbarrier::complete_tx::bytes " \
                 "[%0], [%1], %2, [%3];" \
                 :: "r"((uint32_t)(dst)), "l"(src), "r"((uint32_t)(bytes)), \
                    "r"((uint32_t)(mbar)) : "memory")
#define LDMATRIX_X4(r0, r1, r2, r3, addr) \
    asm volatile("ldmatrix.sync.aligned.m8n8.x4.shared.b16 {%0,%1,%2,%3}, [%4];" \
                 : "=r"(r0), "=r"(r1), "=r"(r2), "=r"(r3) : "r"(addr))
#define MMA_F16(d, a, b) \
    asm volatile("mma.sync.aligned.m16n8k16.row.col.f32.f16.f16.f32 " \
                 "{%0,%1,%2,%3}, {%4,%5,%6,%7}, {%8,%9}, {%0,%1,%2,%3};" \
                 : "+f"((d)[0]), "+f"((d)[1]), "+f"((d)[2]), "+f"((d)[3]) \
                 : "r"((a)[0]), "r"((a)[1]), "r"((a)[2]), "r"((a)[3]), \
                   "r"((b)[0]), "r"((b)[1]))

// ---------------- smem layout ----------------
#define SM_BAR   0                    // full[s] at 16*s, empty[s] at 16*s+8
#define SM_BIAS  128                  // 128 floats
#define SM_TILES 1024
#define T_AH     0
#define T_BH     16384
#define STAGE_BYTES 32768             // 2 x 16KB
#define SMEM_TOTAL (SM_TILES + NSTAGE * STAGE_BYTES)   // 99328 (2 CTAs/SM)

// chunk-major, swizzled byte offset for (row, k0): 4 consecutive halves (8B)
__device__ __forceinline__ size_t scratch_off(int nTotRows, int row, int k0) {
    const int chunk = k0 >> 6;
    const int kc = k0 & 63;
    const int ci = kc >> 3;
    const int h8 = (kc >> 2) & 1;
    return ((size_t)chunk * nTotRows + row) * 128 + ((ci ^ (row & 7)) << 4) + h8 * 8;
}

__device__ __forceinline__ uint2 pack_h4(const float v[4]) {
    uint16_t h[4];
    #pragma unroll
    for (int i = 0; i < 4; i++) {
        __half hv = __float2half_rn(v[i]);
        h[i] = *(uint16_t*)&hv;
    }
    return make_uint2((uint32_t)h[0] | ((uint32_t)h[1] << 16),
                      (uint32_t)h[2] | ((uint32_t)h[3] << 16));
}

// ---------------- merged prep kernel (4 rows/block, MLP>=4 per thread) ----
#define XBLK (NROWS / 4)       // 2048
#define WBLK (DIM / 4)         // 512
__global__ void prep_all(const float* __restrict__ x,
                         const int* __restrict__ ids,
                         const float* __restrict__ emb,
                         const float* __restrict__ Wt,
                         const float* __restrict__ Wrc,
                         const float* __restrict__ brc) {
    const int b = blockIdx.x;
    const int c4 = threadIdx.x;           // 512 threads = 512 float4 per row
    if (b < XBLK) {
        const int row0 = b * 4;
        float4 xv[4], ev[4];
        int id[4];
        #pragma unroll
        for (int r = 0; r < 4; r++) {
            id[r] = ids[row0 + r];
            xv[r] = ((const float4*)(x + (size_t)(row0 + r) * DIM))[c4];
        }
        #pragma unroll
        for (int r = 0; r < 4; r++)
            ev[r] = ((const float4*)(emb + (size_t)id[r] * DIM))[c4];
        #pragma unroll
        for (int r = 0; r < 4; r++) {
            float v[4] = {xv[r].x + ev[r].x, xv[r].y + ev[r].y,
                          xv[r].z + ev[r].z, xv[r].w + ev[r].w};
            *(uint2*)((char*)g_Ah + scratch_off(NROWS, row0 + r, c4 * 4)) = pack_h4(v);
        }
    } else if (b < XBLK + WBLK) {
        const int row0 = (b - XBLK) * 4;
        float4 wv[4];
        #pragma unroll
        for (int r = 0; r < 4; r++)
            wv[r] = ((const float4*)(Wt + (size_t)(row0 + r) * DIM))[c4];
        #pragma unroll
        for (int r = 0; r < 4; r++) {
            float v[4] = {wv[r].x, wv[r].y, wv[r].z, wv[r].w};
            *(uint2*)((char*)g_Wh + scratch_off(DIM, row0 + r, c4 * 4)) = pack_h4(v);
        }
    } else {
        __shared__ float red[32];
        float s = 0.f;
        for (int i = c4; i < DIM; i += 512) s += Wrc[i];
        #pragma unroll
        for (int o = 16; o > 0; o >>= 1) s += __shfl_down_sync(0xffffffffu, s, o);
        if ((c4 & 31) == 0) red[c4 >> 5] = s;
        __syncthreads();
        if (c4 < 32) {
            float v = (c4 < 16) ? red[c4] : 0.f;
            #pragma unroll
            for (int o = 8; o > 0; o >>= 1) v += __shfl_down_sync(0xffffffffu, v, o);
            if (c4 == 0)
                g_zeta = 1.f / (1.f + expf(-(REL_CONTEXT * v + brc[0])));
        }
    }
}

// ---------------- main MMA kernel (round-6 proven config) ----------------
__global__ __launch_bounds__(256, 2)
void redaf_mma(const float* __restrict__ mw,
               const float* __restrict__ bt,
               float* __restrict__ out) {
    extern __shared__ char smem[];
    const uint32_t sb = smem_to_u32(smem);
    const int tid = threadIdx.x;
    const int wid = tid >> 5;
    const int lid = tid & 31;

    const int colBase = blockIdx.x * BN;
    const int rowBase = blockIdx.y * BM;

    if (tid == 0) {
        #pragma unroll
        for (int s = 0; s < NSTAGE; s++) {
            MBARRIER_INIT(sb + SM_BAR + 16 * s, 1);        // full: expect_tx
            MBARRIER_INIT(sb + SM_BAR + 16 * s + 8, 8);    // empty: 8 warps
        }
    }
    if (tid < BN) ((float*)(smem + SM_BIAS))[tid] = bt[colBase + tid];
    __syncthreads();

    // ---- producer: 2 bulk copies of 16KB per chunk ----
    auto produce = [&](int c) {
        const int s = c % NSTAGE;
        const uint32_t stB = sb + SM_TILES + s * STAGE_BYTES;
        const uint32_t fb = sb + SM_BAR + 16 * s;
        MBARRIER_EXPECT_TX(fb, STAGE_BYTES);
        BULK_G2S(stB + T_AH,
                 (const char*)g_Ah + ((size_t)c * NROWS + rowBase) * 128, 16384, fb);
        BULK_G2S(stB + T_BH,
                 (const char*)g_Wh + ((size_t)c * DIM + colBase) * 128, 16384, fb);
    };

    // prefill stages 0,1 (chunk 2 produced inside iteration 0)
    if (lid == 0 && wid < NSTAGE - 1) produce(wid);

    // ---- per-lane ldmatrix address pieces ----
    const int warpM = wid & 1;
    const int warpN = wid >> 1;
    const int aRowL = warpM * 64 + (lid & 15);
    const int aKhalf = lid >> 4;
    const int bRowL = warpN * 32 + (lid & 7) + ((lid >> 4) & 1) * 8;
    const int bKhalf = (lid >> 3) & 1;

    float acc[4][4][4];
    #pragma unroll
    for (int i = 0; i < 4; i++)
        #pragma unroll
        for (int j = 0; j < 4; j++)
            #pragma unroll
            for (int k = 0; k < 4; k++) acc[i][j][k] = 0.f;

    #pragma unroll 1
    for (int c = 0; c < NCH; c++) {
        const int s = c % NSTAGE;
        const uint32_t par = (c / NSTAGE) & 1;
        const uint32_t fullB = sb + SM_BAR + 16 * s;
        const uint32_t emptyB = fullB + 8;
        MBARRIER_WAIT_PARITY(fullB, par);

        const uint32_t stBase = sb + SM_TILES + s * STAGE_BYTES;
        #pragma unroll
        for (int ks = 0; ks < BK / 16; ks++) {
            uint32_t ah[4][4], bh[4][2];
            #pragma unroll
            for (int mt = 0; mt < 4; mt++) {
                const int row = aRowL + mt * 16;
                const int ch = 2 * ks + aKhalf;
                const uint32_t off = row * 128 + ((ch ^ (row & 7)) << 4);
                LDMATRIX_X4(ah[mt][0], ah[mt][1], ah[mt][2], ah[mt][3],
                            stBase + T_AH + off);
            }
            #pragma unroll
            for (int p = 0; p < 2; p++) {
                const int row = bRowL + p * 16;
                const int ch = 2 * ks + bKhalf;
                const uint32_t off = row * 128 + ((ch ^ (row & 7)) << 4);
                LDMATRIX_X4(bh[2 * p][0], bh[2 * p][1], bh[2 * p + 1][0], bh[2 * p + 1][1],
                            stBase + T_BH + off);
            }
            #pragma unroll
            for (int mt = 0; mt < 4; mt++)
                #pragma unroll
                for (int nt = 0; nt < 4; nt++) MMA_F16(acc[mt][nt], ah[mt], bh[nt]);
        }

        if (lid == 0) {
            MBARRIER_ARRIVE(emptyB);                  // this warp done reading chunk c
            const int t = (c + 2) % NSTAGE;
            if (wid == t && c + 2 < NCH) {
                if (c + 2 >= NSTAGE) {                // stage t had prior readers
                    MBARRIER_WAIT_PARITY(sb + SM_BAR + 16 * t + 8,
                                         (uint32_t)(((c - 1) / NSTAGE) & 1));
                }
                produce(c + 2);
            }
        }
    }

    // ---- epilogue: bias -> relu -> mw*zeta -> relu ----
    const float zeta = g_zeta;
    const float mwz0 = mw[0] * zeta;
    const float mwz1 = mw[1] * zeta;
    const float* bsm = (const float*)(smem + SM_BIAS);

    #pragma unroll
    for (int mt = 0; mt < 4; mt++) {
        #pragma unroll
        for (int nt = 0; nt < 4; nt++) {
            const int m0 = rowBase + warpM * 64 + mt * 16 + (lid >> 2);
            const int cLoc = warpN * 32 + nt * 8 + 2 * (lid & 3);
            const float b0 = bsm[cLoc], b1 = bsm[cLoc + 1];
            const float mz = (m0 & 1) ? mwz1 : mwz0;
            float2 o0, o1;
            o0.x = fmaxf(mz * fmaxf(acc[mt][nt][0] + b0, 0.f), 0.f);
            o0.y = fmaxf(mz * fmaxf(acc[mt][nt][1] + b1, 0.f), 0.f);
            o1.x = fmaxf(mz * fmaxf(acc[mt][nt][2] + b0, 0.f), 0.f);
            o1.y = fmaxf(mz * fmaxf(acc[mt][nt][3] + b1, 0.f), 0.f);
            float* p0 = out + (size_t)m0 * DIM + colBase + cLoc;
            *(float2*)p0 = o0;
            *(float2*)(p0 + (size_t)8 * DIM) = o1;
        }
    }
}

// ---------------- launch ----------------
extern "C" void kernel_launch(void* const* d_in, const int* in_sizes, int n_in,
                              void* d_out, int out_size) {
    const float* x   = (const float*)d_in[0];
    const int*   ids = (const int*)  d_in[1];
    const float* mw  = (const float*)d_in[2];
    const float* emb = (const float*)d_in[3];
    const float* Wt  = (const float*)d_in[4];
    const float* bt  = (const float*)d_in[5];
    const float* Wrc = (const float*)d_in[6];
    const float* brc = (const float*)d_in[7];

    cudaFuncSetAttribute(redaf_mma, cudaFuncAttributeMaxDynamicSharedMemorySize,
                         SMEM_TOTAL);

    prep_all<<<XBLK + WBLK + 1, 512>>>(x, ids, emb, Wt, Wrc, brc);

    dim3 grid(DIM / BN, NROWS / BM);   // (16, 64) = 1024 CTAs
    redaf_mma<<<grid, 256, SMEM_TOTAL>>>(mw, bt, (float*)d_out);
}

// round 9
// speedup vs baseline: 1.1507x; 1.0264x over previous
#include <cuda_runtime.h>
#include <cuda_fp16.h>
#include <cstdint>

#define REL_CONTEXT 0.2f

// ---------------- problem dims (fixed) ----------------
#define NROWS 8192
#define DIM   2048
#define BM    128
#define BN    128
#define BK    64
#define NCH   (DIM / BK)       // 32
#define NSTAGE 4

// ---------------- scratch ----------------
// A: chunk-major, pre-swizzled fp16 (as rounds 4-8)
__device__ __align__(128) __half g_Ah[(size_t)NROWS * DIM];
// W: fragment-major fp16 pairs. For (chunk ch, colBlk cb, warpN wN, ks):
//   1024-byte block at group*1024, group = ((ch*16+cb)*4+wN)*4+ks;
//   within: lane*32 + j*4, j = q*2+i  ->  b32 = pack( W[n][k], W[n][k+1] )
//   n = cb*128 + wN*32 + q*8 + lane/4,  k = ch*64 + ks*16 + i*8 + (lane%4)*2
__device__ __align__(128) uint32_t g_WhF[(size_t)DIM * DIM / 2];
__device__ float g_zeta;

// ---------------- PTX helpers (base-target only) ----------------
__device__ __forceinline__ uint32_t smem_to_u32(const void* p) {
    uint32_t a;
    asm("{ .reg .u64 t; cvta.to.shared.u64 t, %1; cvt.u32.u64 %0, t; }"
        : "=r"(a) : "l"(p));
    return a;
}
#define MBARRIER_INIT(addr, cnt) \
    asm volatile("mbarrier.init.shared.b64 [%0], %1;" :: "r"((uint32_t)(addr)), "r"((uint32_t)(cnt)) : "memory")
#define MBARRIER_ARRIVE(addr) \
    asm volatile("mbarrier.arrive.shared.b64 _, [%0];" :: "r"((uint32_t)(addr)) : "memory")
#define MBARRIER_EXPECT_TX(addr, bytes) \
    asm volatile("mbarrier.arrive.expect_tx.shared.b64 _, [%0], %1;" \
                 :: "r"((uint32_t)(addr)), "r"((uint32_t)(bytes)) : "memory")
#define MBARRIER_WAIT_PARITY(addr, par) do { \
    uint32_t _m = (uint32_t)(addr); uint32_t _p = (uint32_t)(par); uint32_t _d; \
    asm volatile("{\n\t.reg .pred p;\n\t" \
        "mbarrier.try_wait.parity.acquire.cta.shared::cta.b64 p, [%1], %2;\n\t" \
        "selp.b32 %0, 1, 0, p;\n\t}" : "=r"(_d) : "r"(_m), "r"(_p) : "memory"); \
    if (!_d) { \
        asm volatile("{\n\t.reg .pred P1;\n\t" \
            "WL_%=:\n\t" \
            "mbarrier.try_wait.parity.acquire.cta.shared::cta.b64 P1, [%0], %1, 0x989680;\n\t" \
            "@P1 bra.uni WD_%=;\n\tbra.uni WL_%=;\n\tWD_%=:\n\t}" \
            :: "r"(_m), "r"(_p) : "memory"); \
    } } while (0)
#define BULK_G2S(dst, src, bytes, mbar) \
    asm volatile("cp.async.bulk.shared::cluster.global.mbarrier::complete_tx::bytes " \
                 "[%0], [%1], %2, [%3];" \
                 :: "r"((uint32_t)(dst)), "l"(src), "r"((uint32_t)(bytes)), \
                    "r"((uint32_t)(mbar)) : "memory")
#define LDMATRIX_X4(r0, r1, r2, r3, addr) \
    asm volatile("ldmatrix.sync.aligned.m8n8.x4.shared.b16 {%0,%1,%2,%3}, [%4];" \
                 : "=r"(r0), "=r"(r1), "=r"(r2), "=r"(r3) : "r"(addr))
#define MMA_F16(d, a, b) \
    asm volatile("mma.sync.aligned.m16n8k16.row.col.f32.f16.f16.f32 " \
                 "{%0,%1,%2,%3}, {%4,%5,%6,%7}, {%8,%9}, {%0,%1,%2,%3};" \
                 : "+f"((d)[0]), "+f"((d)[1]), "+f"((d)[2]), "+f"((d)[3]) \
                 : "r"((a)[0]), "r"((a)[1]), "r"((a)[2]), "r"((a)[3]), \
                   "r"((b)[0]), "r"((b)[1]))

// ---------------- smem layout ----------------
#define SM_BAR   0                    // full[s] at 16*s, empty[s] at 16*s+8
#define SM_BIAS  128                  // 128 floats
#define SM_TILES 1024
#define STAGE_BYTES 16384             // A tile only
#define SMEM_TOTAL (SM_TILES + NSTAGE * STAGE_BYTES)   // 66560 (2 CTAs/SM)

// chunk-major, swizzled byte offset for (row, k0): 4 consecutive halves (8B)
__device__ __forceinline__ size_t scratch_off(int nTotRows, int row, int k0) {
    const int chunk = k0 >> 6;
    const int kc = k0 & 63;
    const int ci = kc >> 3;
    const int h8 = (kc >> 2) & 1;
    return ((size_t)chunk * nTotRows + row) * 128 + ((ci ^ (row & 7)) << 4) + h8 * 8;
}

__device__ __forceinline__ uint2 pack_h4(const float v[4]) {
    uint16_t h[4];
    #pragma unroll
    for (int i = 0; i < 4; i++) {
        __half hv = __float2half_rn(v[i]);
        h[i] = *(uint16_t*)&hv;
    }
    return make_uint2((uint32_t)h[0] | ((uint32_t)h[1] << 16),
                      (uint32_t)h[2] | ((uint32_t)h[3] << 16));
}

__device__ __forceinline__ uint32_t pack_h2(float a, float b) {
    __half ha = __float2half_rn(a), hb = __float2half_rn(b);
    return (uint32_t)*(uint16_t*)&ha | ((uint32_t)*(uint16_t*)&hb << 16);
}

// ---------------- merged prep kernel ----------------
#define XBLK  (NROWS / 4)      // 2048 blocks: x+emb -> g_Ah (4 rows/block)
#define WGRPS (32 * 16 * 4 * 4) // 8192 fragment groups
#define WFBLK (WGRPS / 8)      // 1024 blocks: Wt -> g_WhF (8 groups/block)
__global__ void prep_all(const float* __restrict__ x,
                         const int* __restrict__ ids,
                         const float* __restrict__ emb,
                         const float* __restrict__ Wt,
                         const float* __restrict__ Wrc,
                         const float* __restrict__ brc) {
    const int b = blockIdx.x;
    const int c4 = threadIdx.x;           // 512 threads
    if (b < XBLK) {
        const int row0 = b * 4;
        float4 xv[4], ev[4];
        int id[4];
        #pragma unroll
        for (int r = 0; r < 4; r++) {
            id[r] = ids[row0 + r];
            xv[r] = ((const float4*)(x + (size_t)(row0 + r) * DIM))[c4];
        }
        #pragma unroll
        for (int r = 0; r < 4; r++)
            ev[r] = ((const float4*)(emb + (size_t)id[r] * DIM))[c4];
        #pragma unroll
        for (int r = 0; r < 4; r++) {
            float v[4] = {xv[r].x + ev[r].x, xv[r].y + ev[r].y,
                          xv[r].z + ev[r].z, xv[r].w + ev[r].w};
            *(uint2*)((char*)g_Ah + scratch_off(NROWS, row0 + r, c4 * 4)) = pack_h4(v);
        }
    } else if (b < XBLK + WFBLK) {
        // W fragment-major conversion: 8 groups per block, 64 threads per group
        const int g = (b - XBLK) * 8 + (c4 >> 6);
        const int t = c4 & 63;
        const int ks = g & 3;
        const int wN = (g >> 2) & 3;
        const int cb = (g >> 4) & 15;
        const int ch = g >> 8;
        const int lane = t >> 1;
        const int half = t & 1;                 // q in {0,1} or {2,3}
        const int n0 = cb * 128 + wN * 32 + half * 16 + (lane >> 2);
        const int k0 = ch * 64 + ks * 16 + (lane & 3) * 2;
        uint32_t w[4];
        #pragma unroll
        for (int dq = 0; dq < 2; dq++) {        // q = half*2 + dq
            #pragma unroll
            for (int i = 0; i < 2; i++) {
                const float* p = Wt + (size_t)(n0 + dq * 8) * DIM + k0 + i * 8;
                float2 wv = *(const float2*)p;
                w[dq * 2 + i] = pack_h2(wv.x, wv.y);
            }
        }
        *(uint4*)((char*)g_WhF + (size_t)g * 1024 + lane * 32 + half * 16) =
            make_uint4(w[0], w[1], w[2], w[3]);
    } else {
        __shared__ float red[32];
        float s = 0.f;
        for (int i = c4; i < DIM; i += 512) s += Wrc[i];
        #pragma unroll
        for (int o = 16; o > 0; o >>= 1) s += __shfl_down_sync(0xffffffffu, s, o);
        if ((c4 & 31) == 0) red[c4 >> 5] = s;
        __syncthreads();
        if (c4 < 32) {
            float v = (c4 < 16) ? red[c4] : 0.f;
            #pragma unroll
            for (int o = 8; o > 0; o >>= 1) v += __shfl_down_sync(0xffffffffu, v, o);
            if (c4 == 0)
                g_zeta = 1.f / (1.f + expf(-(REL_CONTEXT * v + brc[0])));
        }
    }
}

// ---------------- main MMA kernel: A via smem/ldmatrix, B via LDG ----------
__global__ __launch_bounds__(256, 2)
void redaf_mma(const float* __restrict__ mw,
               const float* __restrict__ bt,
               float* __restrict__ out) {
    extern __shared__ char smem[];
    const uint32_t sb = smem_to_u32(smem);
    const int tid = threadIdx.x;
    const int wid = tid >> 5;
    const int lid = tid & 31;

    const int cb      = blockIdx.x;        // col block (BN=128)
    const int colBase = cb * BN;
    const int rowBase = blockIdx.y * BM;

    if (tid == 0) {
        #pragma unroll
        for (int s = 0; s < NSTAGE; s++) {
            MBARRIER_INIT(sb + SM_BAR + 16 * s, 1);        // full: expect_tx
            MBARRIER_INIT(sb + SM_BAR + 16 * s + 8, 8);    // empty: 8 warps
        }
    }
    if (tid < BN) ((float*)(smem + SM_BIAS))[tid] = bt[colBase + tid];
    __syncthreads();

    // ---- producer: ONE 16KB bulk copy (A) per chunk ----
    auto produce = [&](int c) {
        const int s = c & 3;
        const uint32_t fb = sb + SM_BAR + 16 * s;
        MBARRIER_EXPECT_TX(fb, STAGE_BYTES);
        BULK_G2S(sb + SM_TILES + s * STAGE_BYTES,
                 (const char*)g_Ah + ((size_t)c * NROWS + rowBase) * 128, 16384, fb);
    };

    // prefill chunks 0..2 into stages 0..2 (chunk 3 produced in iteration 0)
    if (lid == 0 && wid < NSTAGE - 1) produce(wid);

    // ---- warp grid 2(M) x 4(N); warp tile 64x32 (round-6 proven) ----
    const int warpM = wid & 1;
    const int warpN = wid >> 1;
    const int aRowL = warpM * 64 + (lid & 15);
    const int aKhalf = lid >> 4;

    // B fragment gmem base for this (cb, warpN, lane)
    const char* wf = (const char*)g_WhF + (size_t)(cb * 16 + warpN * 4) * 1024 + lid * 32;

    uint32_t bb[2][8];
    auto ldB = [&](int step, int buf) {
        const char* p = wf + (size_t)(step >> 2) * 262144 + (size_t)(step & 3) * 1024;
        uint4 u0 = *(const uint4*)p;
        uint4 u1 = *(const uint4*)(p + 16);
        bb[buf][0] = u0.x; bb[buf][1] = u0.y; bb[buf][2] = u0.z; bb[buf][3] = u0.w;
        bb[buf][4] = u1.x; bb[buf][5] = u1.y; bb[buf][6] = u1.z; bb[buf][7] = u1.w;
    };
    ldB(0, 0);                      // preload step 0

    float acc[4][4][4];
    #pragma unroll
    for (int i = 0; i < 4; i++)
        #pragma unroll
        for (int j = 0; j < 4; j++)
            #pragma unroll
            for (int k = 0; k < 4; k++) acc[i][j][k] = 0.f;

    #pragma unroll 1
    for (int c = 0; c < NCH; c++) {
        const int s = c & 3;
        const uint32_t par = (c >> 2) & 1;
        const uint32_t fullB = sb + SM_BAR + 16 * s;
        const uint32_t emptyB = fullB + 8;
        MBARRIER_WAIT_PARITY(fullB, par);

        const uint32_t stBase = sb + SM_TILES + s * STAGE_BYTES;
        #pragma unroll
        for (int ks = 0; ks < BK / 16; ks++) {
            const int cur = ks & 1;                 // step = 4c+ks, 4c even
            // prefetch next step's B fragments (gmem, no barrier dependency)
            if (c < NCH - 1 || ks < 3) ldB(c * 4 + ks + 1, cur ^ 1);
            // A fragments via ldmatrix
            uint32_t ah[4][4];
            #pragma unroll
            for (int mt = 0; mt < 4; mt++) {
                const int row = aRowL + mt * 16;
                const int ch = 2 * ks + aKhalf;
                const uint32_t off = row * 128 + ((ch ^ (row & 7)) << 4);
                LDMATRIX_X4(ah[mt][0], ah[mt][1], ah[mt][2], ah[mt][3],
                            stBase + off);
            }
            #pragma unroll
            for (int mt = 0; mt < 4; mt++)
                #pragma unroll
                for (int nt = 0; nt < 4; nt++)
                    MMA_F16(acc[mt][nt], ah[mt], (bb[cur] + nt * 2));
        }

        if (lid == 0) {
            MBARRIER_ARRIVE(emptyB);                // this warp done with chunk c
            const int t = (c + 3) & 3;
            if (wid == t && c + 3 < NCH) {
                if (c + 3 >= NSTAGE) {              // stage t had prior readers
                    MBARRIER_WAIT_PARITY(sb + SM_BAR + 16 * t + 8,
                                         (uint32_t)(((c - 1) >> 2) & 1));
                }
                produce(c + 3);
            }
        }
    }

    // ---- epilogue: bias -> relu -> mw*zeta -> relu ----
    const float zeta = g_zeta;
    const float mwz0 = mw[0] * zeta;
    const float mwz1 = mw[1] * zeta;
    const float* bsm = (const float*)(smem + SM_BIAS);

    #pragma unroll
    for (int mt = 0; mt < 4; mt++) {
        #pragma unroll
        for (int nt = 0; nt < 4; nt++) {
            const int m0 = rowBase + warpM * 64 + mt * 16 + (lid >> 2);
            const int cLoc = warpN * 32 + nt * 8 + 2 * (lid & 3);
            const float b0 = bsm[cLoc], b1 = bsm[cLoc + 1];
            const float mz = (m0 & 1) ? mwz1 : mwz0;
            float2 o0, o1;
            o0.x = fmaxf(mz * fmaxf(acc[mt][nt][0] + b0, 0.f), 0.f);
            o0.y = fmaxf(mz * fmaxf(acc[mt][nt][1] + b1, 0.f), 0.f);
            o1.x = fmaxf(mz * fmaxf(acc[mt][nt][2] + b0, 0.f), 0.f);
            o1.y = fmaxf(mz * fmaxf(acc[mt][nt][3] + b1, 0.f), 0.f);
            float* p0 = out + (size_t)m0 * DIM + colBase + cLoc;
            *(float2*)p0 = o0;
            *(float2*)(p0 + (size_t)8 * DIM) = o1;
        }
    }
}

// ---------------- launch ----------------
extern "C" void kernel_launch(void* const* d_in, const int* in_sizes, int n_in,
                              void* d_out, int out_size) {
    const float* x   = (const float*)d_in[0];
    const int*   ids = (const int*)  d_in[1];
    const float* mw  = (const float*)d_in[2];
    const float* emb = (const float*)d_in[3];
    const float* Wt  = (const float*)d_in[4];
    const float* bt  = (const float*)d_in[5];
    const float* Wrc = (const float*)d_in[6];
    const float* brc = (const float*)d_in[7];

    cudaFuncSetAttribute(redaf_mma, cudaFuncAttributeMaxDynamicSharedMemorySize,
                         SMEM_TOTAL);

    prep_all<<<XBLK + WFBLK + 1, 512>>>(x, ids, emb, Wt, Wrc, brc);

    dim3 grid(DIM / BN, NROWS / BM);   // (16, 64) = 1024 CTAs
    redaf_mma<<<grid, 256, SMEM_TOTAL>>>(mw, bt, (float*)d_out);
}